// round 8
// baseline (speedup 1.0000x reference)
#include <cuda_runtime.h>
#include <cstdint>

#define BB    1024
#define INF   4096
#define OUTF  4096
#define KF    64
#define TOPK  64

// 64MB transposed-weight scratch: WT[i*OUTF + o] = W[o*INF + i]
__device__ float g_wt[(size_t)INF * OUTF];

// ---------------------------------------------------------------------------
// Kernel 1: tiled transpose W(OUT,IN) -> WT(IN,OUT)
// ---------------------------------------------------------------------------
__global__ void transpose_kernel(const float* __restrict__ W) {
    __shared__ float tile[32][33];
    int x = blockIdx.x * 32 + threadIdx.x;   // i
    int y = blockIdx.y * 32 + threadIdx.y;   // o
#pragma unroll
    for (int j = 0; j < 32; j += 8)
        tile[threadIdx.y + j][threadIdx.x] = __ldg(&W[(size_t)(y + j) * INF + x]);
    __syncthreads();
    x = blockIdx.y * 32 + threadIdx.x;       // o
    y = blockIdx.x * 32 + threadIdx.y;       // i
#pragma unroll
    for (int j = 0; j < 32; j += 8)
        g_wt[(size_t)(y + j) * OUTF + x] = tile[threadIdx.x][threadIdx.y + j];
}

// ---------------------------------------------------------------------------
// float <-> order-preserving uint32 key
// ---------------------------------------------------------------------------
__device__ __forceinline__ unsigned f2key(float f) {
    unsigned u = __float_as_uint(f);
    return u ^ ((u & 0x80000000u) ? 0xFFFFFFFFu : 0x80000000u);
}
__device__ __forceinline__ float key2f(unsigned k) {
    unsigned u = k ^ ((k & 0x80000000u) ? 0x80000000u : 0xFFFFFFFFu);
    return __uint_as_float(u);
}

// ---------------------------------------------------------------------------
// Kernel 2: one block per batch row.
//   - 512 threads, each accumulates 8 outputs (2x float4) in registers
//   - exact fp32 gather-matvec over 64 sparse columns (coalesced WT rows)
//   - exact top-64 via 64-bit-composite radix select + bitonic sort
// Composite: (sortable_key(value) << 32) | (OUTF-1-o)
//   -> descending composite order == descending value, ties lower o first,
//      exactly matching jax.lax.top_k.
// ---------------------------------------------------------------------------
__global__ __launch_bounds__(512) void router_kernel(
    const float* __restrict__ x, const float* __restrict__ bias,
    const int* __restrict__ pidx, float* __restrict__ out, int write_idx)
{
    __shared__ float sx[KF];
    __shared__ int   sc[KF];
    __shared__ unsigned hist[256];
    __shared__ unsigned long long s_prefix;
    __shared__ int s_target;
    __shared__ unsigned long long s_top[TOPK];
    __shared__ int s_cnt;

    const int b = blockIdx.x;
    const int tid = threadIdx.x;

    if (tid < KF) { sx[tid] = x[b * KF + tid]; sc[tid] = pidx[b * KF + tid]; }
    if (tid == 0) { s_prefix = 0ULL; s_target = TOPK; s_cnt = 0; }
    __syncthreads();

    // ---- gather matvec: 8 outputs per thread --------------------------------
    const float4* wt4 = (const float4*)g_wt;
    const float4* b4  = (const float4*)bias;
    float4 a0 = b4[tid];          // o = 4*tid .. 4*tid+3
    float4 a1 = b4[512 + tid];    // o = 2048 + 4*tid .. +3

#pragma unroll 8
    for (int k = 0; k < KF; k++) {
        float xv = sx[k];
        const float4* p = wt4 + (size_t)sc[k] * (OUTF / 4);
        float4 w0 = p[tid];
        float4 w1 = p[512 + tid];
        a0.x += xv * w0.x; a0.y += xv * w0.y; a0.z += xv * w0.z; a0.w += xv * w0.w;
        a1.x += xv * w1.x; a1.y += xv * w1.y; a1.z += xv * w1.z; a1.w += xv * w1.w;
    }

    // ---- build 64-bit composites -------------------------------------------
    float v0[4] = {a0.x, a0.y, a0.z, a0.w};
    float v1[4] = {a1.x, a1.y, a1.z, a1.w};
    unsigned long long comp[8];
#pragma unroll
    for (int j = 0; j < 4; j++) {
        comp[j]     = ((unsigned long long)f2key(v0[j]) << 32) |
                      (unsigned)(OUTF - 1 - (4 * tid + j));
        comp[j + 4] = ((unsigned long long)f2key(v1[j]) << 32) |
                      (unsigned)(OUTF - 1 - (2048 + 4 * tid + j));
    }

    // ---- radix select: exact 64th-largest composite (8 passes of 8 bits) ---
    for (int p = 7; p >= 0; p--) {
        if (tid < 256) hist[tid] = 0;
        __syncthreads();
        const unsigned long long prefix_cur = s_prefix;
        const unsigned long long hi_mask = (p == 7) ? 0ULL : (~0ULL << ((p + 1) * 8));
#pragma unroll
        for (int j = 0; j < 8; j++) {
            if ((comp[j] & hi_mask) == prefix_cur)
                atomicAdd(&hist[(unsigned)(comp[j] >> (p * 8)) & 255u], 1u);
        }
        __syncthreads();
        // inclusive suffix sum over hist
        for (int off = 1; off < 256; off <<= 1) {
            unsigned vv = 0;
            if (tid < 256 && tid + off < 256) vv = hist[tid + off];
            __syncthreads();
            if (tid < 256) hist[tid] += vv;
            __syncthreads();
        }
        int tgt = s_target;
        __syncthreads();
        if (tid < 256) {
            unsigned s  = hist[tid];
            unsigned sn = (tid < 255) ? hist[tid + 1] : 0u;
            if ((int)s >= tgt && (int)sn < tgt) {   // unique winner bin
                s_prefix = prefix_cur | ((unsigned long long)tid << (p * 8));
                s_target = tgt - (int)sn;
            }
        }
        __syncthreads();
    }
    const unsigned long long T = s_prefix;  // exact 64th-largest composite

    // ---- collect the 64 winners --------------------------------------------
#pragma unroll
    for (int j = 0; j < 8; j++) {
        if (comp[j] >= T) {
            int pos = atomicAdd(&s_cnt, 1);
            if (pos < TOPK) s_top[pos] = comp[j];
        }
    }
    __syncthreads();

    // ---- bitonic sort descending (64 elements) -----------------------------
    for (int k2 = 2; k2 <= TOPK; k2 <<= 1) {
        for (int j = k2 >> 1; j > 0; j >>= 1) {
            if (tid < TOPK) {
                int ixj = tid ^ j;
                if (ixj > tid) {
                    bool desc = ((tid & k2) == 0);
                    unsigned long long aa = s_top[tid], bb = s_top[ixj];
                    if (desc ? (aa < bb) : (aa > bb)) {
                        s_top[tid] = bb; s_top[ixj] = aa;
                    }
                }
            }
            __syncthreads();
        }
    }

    // ---- write: [B*64 vals][B*64 indices-as-float] -------------------------
    if (tid < TOPK) {
        unsigned long long c = s_top[tid];
        out[b * TOPK + tid] = key2f((unsigned)(c >> 32));
        if (write_idx)
            out[BB * TOPK + b * TOPK + tid] =
                (float)(OUTF - 1 - (int)(c & 0xFFFFFFFFu));
    }
}

// ---------------------------------------------------------------------------
extern "C" void kernel_launch(void* const* d_in, const int* in_sizes, int n_in,
                              void* d_out, int out_size) {
    const float* x    = (const float*)d_in[0];
    const float* w    = (const float*)d_in[1];
    const float* bias = (const float*)d_in[2];
    const int*   pidx = (const int*)d_in[3];
    (void)n_in;

    dim3 tb(32, 8);
    dim3 tg(INF / 32, OUTF / 32);
    transpose_kernel<<<tg, tb>>>(w);

    int write_idx = (out_size >= 2 * BB * TOPK) ? 1 : 0;
    router_kernel<<<BB, 512>>>(x, bias, pidx, (float*)d_out, write_idx);
}